// round 1
// baseline (speedup 1.0000x reference)
#include <cuda_runtime.h>
#include <math.h>

#define B_  2
#define SQ_ 2048
#define SKV_ 2048
#define D_  1024
#define H_  16
#define HD_ 64
#define M_  (B_ * SQ_)   // 4096

// ---------------- scratch (device globals; no allocation allowed) ----------
__device__ float g_q[M_ * D_];
__device__ float g_k[M_ * D_];
__device__ float g_v[M_ * D_];
__device__ float g_ctx[M_ * D_];

// ---------------------------------------------------------------------------
// GEMM: C[M,N] = A[M,K] @ W[N,K]^T + bias[N]   (NT gemm, both K-major)
// mode==1: apply interleaved RoPE per 64-wide head in the epilogue.
// 64x64 CTA tile, 4x4 micro tile, 256 threads, K-slab 16.
// ---------------------------------------------------------------------------
__global__ __launch_bounds__(256) void gemm_bias_rope(
    const float* __restrict__ A, const float* __restrict__ W,
    const float* __restrict__ bias, float* __restrict__ C,
    int M, int N, int K, int rope, int seqLen)
{
    __shared__ float As[16][68];
    __shared__ float Bs[16][68];

    const int tid = threadIdx.x;
    const int tx = tid & 15;
    const int ty = tid >> 4;
    const int rowBase = blockIdx.y * 64;
    const int colBase = blockIdx.x * 64;

    const int lr = tid >> 2;        // 0..63 tile row
    const int lk = (tid & 3) << 2;  // k offset {0,4,8,12}

    const float* Ap = A + (size_t)(rowBase + lr) * K + lk;
    const float* Wp = W + (size_t)(colBase + lr) * K + lk;

    float acc[4][4] = {};

    for (int k0 = 0; k0 < K; k0 += 16) {
        float4 a = *(const float4*)(Ap + k0);
        float4 b = *(const float4*)(Wp + k0);
        As[lk + 0][lr] = a.x; As[lk + 1][lr] = a.y;
        As[lk + 2][lr] = a.z; As[lk + 3][lr] = a.w;
        Bs[lk + 0][lr] = b.x; Bs[lk + 1][lr] = b.y;
        Bs[lk + 2][lr] = b.z; Bs[lk + 3][lr] = b.w;
        __syncthreads();
#pragma unroll
        for (int kk = 0; kk < 16; kk++) {
            float4 av = *(const float4*)&As[kk][ty << 2];
            float4 bv = *(const float4*)&Bs[kk][tx << 2];
            float aa[4] = {av.x, av.y, av.z, av.w};
            float bb[4] = {bv.x, bv.y, bv.z, bv.w};
#pragma unroll
            for (int i = 0; i < 4; i++)
#pragma unroll
                for (int j = 0; j < 4; j++)
                    acc[i][j] = fmaf(aa[i], bb[j], acc[i][j]);
        }
        __syncthreads();
    }

    // epilogue: bias (+ RoPE) + store
    const int colTile = colBase + (tx << 2);
    float bvals[4];
#pragma unroll
    for (int j = 0; j < 4; j++) bvals[j] = bias[colTile + j];

#pragma unroll
    for (int i = 0; i < 4; i++) {
        const int row = rowBase + (ty << 2) + i;
        float c[4];
#pragma unroll
        for (int j = 0; j < 4; j++) c[j] = acc[i][j] + bvals[j];
        if (rope) {
            const int s = row % seqLen;  // position within sequence
#pragma unroll
            for (int jp = 0; jp < 4; jp += 2) {
                const int e = colTile + jp;       // even column
                const int p = (e & (HD_ - 1)) >> 1;  // pair index 0..31
                // freq = ROPE_BASE^(-p/32) = exp(-p * ln(10000)/32)
                const float freq = expf(-(float)p * 0.28782313662425575f);
                const float ang = (float)s * freq;
                float sn, cs;
                sincosf(ang, &sn, &cs);
                const float xe = c[jp], xo = c[jp + 1];
                c[jp]     = xe * cs - xo * sn;
                c[jp + 1] = xe * sn + xo * cs;
            }
        }
        *(float4*)(C + (size_t)row * N + colTile) =
            make_float4(c[0], c[1], c[2], c[3]);
    }
}

// ---------------------------------------------------------------------------
// Flash attention: per (b, h, 64-row Q tile), stream 64-row KV tiles.
// O = softmax(Q K^T / sqrt(HD)) V  -> ctx[b*SQ+s, h*64+d]
// ---------------------------------------------------------------------------
__global__ __launch_bounds__(256) void attn_kernel(
    const float* __restrict__ Q, const float* __restrict__ Kg,
    const float* __restrict__ Vg, float* __restrict__ O)
{
    extern __shared__ float sm[];
    float* Qs = sm;                 // [d][r] 64x68 (transposed, pre-scaled)
    float* Ks = sm + 64 * 68;       // [d][r] 64x68
    float* Vs = sm + 2 * 64 * 68;   // [j][c] 64x68
    float* SS = sm + 3 * 64 * 68;   // [r][c] 64x68
    float* mRow = sm + 4 * 64 * 68; // [64]
    float* lRow = mRow + 64;        // [64]
    float* cRow = lRow + 64;        // [64]

    const int tid = threadIdx.x;
    const int tx = tid & 15;
    const int ty = tid >> 4;
    const int b = blockIdx.z;
    const int h = blockIdx.y;
    const int qBase = blockIdx.x * 64;

    const float* Qp  = Q  + ((size_t)(b * SQ_ + qBase)) * D_ + h * HD_;
    const float* Kp0 = Kg + ((size_t)(b * SKV_)) * D_ + h * HD_;
    const float* Vp0 = Vg + ((size_t)(b * SKV_)) * D_ + h * HD_;

    // load Q tile transposed, folded softmax scale 1/8
#pragma unroll
    for (int it = 0; it < 4; it++) {
        const int idx = tid + it * 256;
        const int r = idx >> 4;
        const int d4 = (idx & 15) << 2;
        float4 v = *(const float4*)(Qp + (size_t)r * D_ + d4);
        Qs[(d4 + 0) * 68 + r] = v.x * 0.125f;
        Qs[(d4 + 1) * 68 + r] = v.y * 0.125f;
        Qs[(d4 + 2) * 68 + r] = v.z * 0.125f;
        Qs[(d4 + 3) * 68 + r] = v.w * 0.125f;
    }
    if (tid < 64) { mRow[tid] = -3.0e38f; lRow[tid] = 0.f; }

    float o[4][4] = {};

    for (int kv = 0; kv < SKV_; kv += 64) {
        // load K (transposed) and V (direct) tiles
#pragma unroll
        for (int it = 0; it < 4; it++) {
            const int idx = tid + it * 256;
            const int r = idx >> 4;
            const int d4 = (idx & 15) << 2;
            float4 kvv = *(const float4*)(Kp0 + (size_t)(kv + r) * D_ + d4);
            Ks[(d4 + 0) * 68 + r] = kvv.x;
            Ks[(d4 + 1) * 68 + r] = kvv.y;
            Ks[(d4 + 2) * 68 + r] = kvv.z;
            Ks[(d4 + 3) * 68 + r] = kvv.w;
            float4 vv = *(const float4*)(Vp0 + (size_t)(kv + r) * D_ + d4);
            *(float4*)&Vs[r * 68 + d4] = vv;
        }
        __syncthreads();

        // S tile = (Q/8) K^T, 4x4 per thread over d=64
        float s[4][4] = {};
#pragma unroll
        for (int d = 0; d < 64; d++) {
            float4 av = *(const float4*)&Qs[d * 68 + (ty << 2)];
            float4 bv = *(const float4*)&Ks[d * 68 + (tx << 2)];
            float aa[4] = {av.x, av.y, av.z, av.w};
            float bb[4] = {bv.x, bv.y, bv.z, bv.w};
#pragma unroll
            for (int i = 0; i < 4; i++)
#pragma unroll
                for (int j = 0; j < 4; j++)
                    s[i][j] = fmaf(aa[i], bb[j], s[i][j]);
        }
#pragma unroll
        for (int i = 0; i < 4; i++)
            *(float4*)&SS[((ty << 2) + i) * 68 + (tx << 2)] =
                make_float4(s[i][0], s[i][1], s[i][2], s[i][3]);
        __syncthreads();

        // online softmax, one thread per row
        if (tid < 64) {
            const int r = tid;
            float m = mRow[r];
            float mx = m;
#pragma unroll 8
            for (int j = 0; j < 64; j++) mx = fmaxf(mx, SS[r * 68 + j]);
            const float corr = __expf(m - mx);
            float l = lRow[r] * corr;
#pragma unroll 8
            for (int j = 0; j < 64; j++) {
                const float p = __expf(SS[r * 68 + j] - mx);
                SS[r * 68 + j] = p;
                l += p;
            }
            mRow[r] = mx; lRow[r] = l; cRow[r] = corr;
        }
        __syncthreads();

        // rescale accumulator, then O += P V
        float cf[4];
#pragma unroll
        for (int i = 0; i < 4; i++) cf[i] = cRow[(ty << 2) + i];
#pragma unroll
        for (int i = 0; i < 4; i++)
#pragma unroll
            for (int j = 0; j < 4; j++) o[i][j] *= cf[i];

#pragma unroll
        for (int j2 = 0; j2 < 64; j2++) {
            float4 vv = *(const float4*)&Vs[j2 * 68 + (tx << 2)];
#pragma unroll
            for (int i = 0; i < 4; i++) {
                const float p = SS[((ty << 2) + i) * 68 + j2];
                o[i][0] = fmaf(p, vv.x, o[i][0]);
                o[i][1] = fmaf(p, vv.y, o[i][1]);
                o[i][2] = fmaf(p, vv.z, o[i][2]);
                o[i][3] = fmaf(p, vv.w, o[i][3]);
            }
        }
        __syncthreads();
    }

    // normalize + store
#pragma unroll
    for (int i = 0; i < 4; i++) {
        const int r = (ty << 2) + i;
        const float inv = 1.0f / lRow[r];
        float4 ov = make_float4(o[i][0] * inv, o[i][1] * inv,
                                o[i][2] * inv, o[i][3] * inv);
        *(float4*)(O + (size_t)(b * SQ_ + qBase + r) * D_ + h * HD_ + (tx << 2)) = ov;
    }
}

// ---------------------------------------------------------------------------
extern "C" void kernel_launch(void* const* d_in, const int* in_sizes, int n_in,
                              void* d_out, int out_size)
{
    const float* x_q  = (const float*)d_in[0];
    const float* x_kv = (const float*)d_in[1];
    const float* wq   = (const float*)d_in[2];
    const float* bq   = (const float*)d_in[3];
    const float* wk   = (const float*)d_in[4];
    const float* bk   = (const float*)d_in[5];
    const float* wv   = (const float*)d_in[6];
    const float* bv   = (const float*)d_in[7];
    const float* wo   = (const float*)d_in[8];
    const float* bo   = (const float*)d_in[9];
    float* out = (float*)d_out;

    float *gq, *gk, *gv, *gctx;
    cudaGetSymbolAddress((void**)&gq, g_q);
    cudaGetSymbolAddress((void**)&gk, g_k);
    cudaGetSymbolAddress((void**)&gv, g_v);
    cudaGetSymbolAddress((void**)&gctx, g_ctx);

    const int smem_attn = (4 * 64 * 68 + 3 * 64) * sizeof(float);  // 70400 B
    cudaFuncSetAttribute(attn_kernel,
                         cudaFuncAttributeMaxDynamicSharedMemorySize, smem_attn);

    dim3 gg(D_ / 64, M_ / 64);  // (16, 64)
    dim3 bb(256);

    // projections (RoPE fused into Q/K epilogues)
    gemm_bias_rope<<<gg, bb>>>(x_q,  wq, bq, gq, M_, D_, D_, 1, SQ_);
    gemm_bias_rope<<<gg, bb>>>(x_kv, wk, bk, gk, M_, D_, D_, 1, SKV_);
    gemm_bias_rope<<<gg, bb>>>(x_kv, wv, bv, gv, M_, D_, D_, 0, SKV_);

    // attention
    dim3 ga(SQ_ / 64, H_, B_);  // (32, 16, 2)
    attn_kernel<<<ga, bb, smem_attn>>>(gq, gk, gv, gctx);

    // output projection
    gemm_bias_rope<<<gg, bb>>>(gctx, wo, bo, out, M_, D_, D_, 0, SQ_);
}

// round 3
// speedup vs baseline: 3.5005x; 3.5005x over previous
#include <cuda_runtime.h>
#include <cstdint>
#include <math.h>

#define B_  2
#define SQ_ 2048
#define SKV_ 2048
#define D_  1024
#define H_  16
#define HD_ 64
#define M_  (B_ * SQ_)   // 4096

// ---------------- scratch (device globals; no allocation allowed) ----------
__device__ float g_q[M_ * D_];
__device__ float g_k[M_ * D_];
__device__ float g_v[M_ * D_];
__device__ float g_vt[M_ * D_];    // V transposed per (b,h): [d][token]
__device__ float g_ctx[M_ * D_];
__device__ float2 g_rope[SQ_ * (HD_ / 2)];

// ===========================================================================
// helpers (plain sm_80+ features only: mma.sync, ldmatrix, cp.async)
// ===========================================================================
__device__ __forceinline__ uint32_t smem_u32(const void* p) {
    uint32_t a;
    asm("{ .reg .u64 t; cvta.to.shared.u64 t, %1; cvt.u32.u64 %0, t; }"
        : "=r"(a) : "l"(p));
    return a;
}
__device__ __forceinline__ float tf32r(float x) {
    uint32_t u = __float_as_uint(x), r;
    asm("cvt.rna.tf32.f32 %0, %1;" : "=r"(r) : "r"(u));
    return __uint_as_float(r);
}
__device__ __forceinline__ float4 tf32r4(float4 v) {
    return make_float4(tf32r(v.x), tf32r(v.y), tf32r(v.z), tf32r(v.w));
}
__device__ __forceinline__ void ldsm4(uint32_t* r, uint32_t addr) {
    asm volatile("ldmatrix.sync.aligned.m8n8.x4.shared.b16 {%0,%1,%2,%3}, [%4];"
        : "=r"(r[0]), "=r"(r[1]), "=r"(r[2]), "=r"(r[3]) : "r"(addr));
}
__device__ __forceinline__ void mma_tf32(float* d, const uint32_t* a, const uint32_t* b) {
    asm volatile(
        "mma.sync.aligned.m16n8k8.row.col.f32.tf32.tf32.f32 "
        "{%0,%1,%2,%3}, {%4,%5,%6,%7}, {%8,%9}, {%0,%1,%2,%3};"
        : "+f"(d[0]), "+f"(d[1]), "+f"(d[2]), "+f"(d[3])
        : "r"(a[0]), "r"(a[1]), "r"(a[2]), "r"(a[3]), "r"(b[0]), "r"(b[1]));
}
__device__ __forceinline__ void cp16(uint32_t dst, const void* src) {
    asm volatile("cp.async.cg.shared.global [%0], [%1], 16;"
        :: "r"(dst), "l"(src));
}
#define CP_COMMIT() asm volatile("cp.async.commit_group;" ::: "memory")
#define CP_WAIT(n)  asm volatile("cp.async.wait_group %0;" :: "n"(n) : "memory")

// ===========================================================================
// RoPE table
// ===========================================================================
__global__ void rope_init_kernel(float2* tab) {
    int i = blockIdx.x * blockDim.x + threadIdx.x;
    if (i < SQ_ * (HD_ / 2)) {
        int s = i >> 5, p = i & 31;
        float freq = expf(-(float)p * 0.28782313662425575f);
        float sn, cs;
        sincosf((float)s * freq, &sn, &cs);
        tab[i] = make_float2(cs, sn);
    }
}

// ===========================================================================
// tf32 mma GEMM: C[M,N] = A[M,K] @ W[N,K]^T + bias (+RoPE) (+tf32 store)
// CTA 128x128, 8 warps (32m x 64n each), K-slab 32, double-buffered smem.
// ===========================================================================
#define GS 36   // smem row stride (floats) for 32-k slab
#define GEMM_SMEM_BYTES (2 * 2 * 128 * GS * 4)   // 73728

__global__ __launch_bounds__(256) void gemm_mma(
    const float* __restrict__ A, const float* __restrict__ W,
    const float* __restrict__ bias, float* __restrict__ C,
    int rope, int docvt, const float2* __restrict__ ropeTab)
{
    extern __shared__ float sm[];
    const int tid = threadIdx.x, lane = tid & 31, wid = tid >> 5;
    const int rowBase = blockIdx.y * 128, colBase = blockIdx.x * 128;
    const int m0 = (wid & 3) * 32, n0 = (wid >> 2) * 64;

    // staging mapping: thread covers rows r0+32j, k cols kq..kq+3
    const int r0 = tid >> 3, kq = (tid & 7) << 2;
    const float* Ab = A + (size_t)(rowBase + r0) * D_ + kq;
    const float* Wb = W + (size_t)(colBase + r0) * D_ + kq;
    int stsOff[4];
#pragma unroll
    for (int j = 0; j < 4; j++) stsOff[j] = (r0 + 32 * j) * GS + kq;

    // fragment address components
    const int rowOff = (lane & 7) + ((lane >> 3) & 1) * 8;
    const int aCol   = (lane >> 4) * 4;
    const int nOff   = (lane & 7) + (lane >> 4) * 8;
    const int bCol   = ((lane >> 3) & 1) * 4;

    const uint32_t smB = smem_u32(sm);

    float4 ra[4], rw[4];
#pragma unroll
    for (int j = 0; j < 4; j++) {
        ra[j] = *(const float4*)(Ab + (size_t)(32 * j) * D_);
        rw[j] = *(const float4*)(Wb + (size_t)(32 * j) * D_);
    }

    float acc[2][8][4] = {};

    for (int i = 0; i < 32; i++) {
        const int buf = i & 1;
        float* tA = sm + buf * (2 * 128 * GS);
        float* tW = tA + 128 * GS;
#pragma unroll
        for (int j = 0; j < 4; j++) {
            *(float4*)&tA[stsOff[j]] = tf32r4(ra[j]);
            *(float4*)&tW[stsOff[j]] = tf32r4(rw[j]);
        }
        __syncthreads();

        if (i + 1 < 32) {
            const size_t k0 = (size_t)(i + 1) * 32;
#pragma unroll
            for (int j = 0; j < 4; j++) {
                ra[j] = *(const float4*)(Ab + (size_t)(32 * j) * D_ + k0);
                rw[j] = *(const float4*)(Wb + (size_t)(32 * j) * D_ + k0);
            }
        }

        const uint32_t aBase = smB + (buf * 2 * 128 * GS) * 4;
        const uint32_t wBase = aBase + 128 * GS * 4;
#pragma unroll
        for (int ks = 0; ks < 4; ks++) {
            uint32_t af[2][4];
            ldsm4(af[0], aBase + (uint32_t)(((m0      + rowOff) * GS + ks * 8 + aCol) * 4));
            ldsm4(af[1], aBase + (uint32_t)(((m0 + 16 + rowOff) * GS + ks * 8 + aCol) * 4));
            uint32_t bf[4][4];
#pragma unroll
            for (int p = 0; p < 4; p++)
                ldsm4(bf[p], wBase + (uint32_t)(((n0 + 16 * p + nOff) * GS + ks * 8 + bCol) * 4));
#pragma unroll
            for (int t = 0; t < 2; t++)
#pragma unroll
                for (int p = 0; p < 4; p++) {
                    mma_tf32(acc[t][2 * p],     af[t], &bf[p][0]);
                    mma_tf32(acc[t][2 * p + 1], af[t], &bf[p][2]);
                }
        }
        __syncthreads();
    }

    // epilogue
#pragma unroll
    for (int t = 0; t < 2; t++) {
        const int rlo = rowBase + m0 + 16 * t + (lane >> 2);
        const int rhi = rlo + 8;
        const int slo = rlo & (SQ_ - 1), shi = rhi & (SQ_ - 1);
#pragma unroll
        for (int j = 0; j < 8; j++) {
            const int col = colBase + n0 + j * 8 + ((lane & 3) << 1);
            const float b0 = __ldg(bias + col), b1 = __ldg(bias + col + 1);
            float v0 = acc[t][j][0] + b0, v1 = acc[t][j][1] + b1;
            float v2 = acc[t][j][2] + b0, v3 = acc[t][j][3] + b1;
            if (rope) {
                const int p = (col & (HD_ - 1)) >> 1;
                const float2 cl = __ldg(ropeTab + slo * 32 + p);
                const float2 ch = __ldg(ropeTab + shi * 32 + p);
                float e = v0, o = v1;
                v0 = e * cl.x - o * cl.y; v1 = e * cl.y + o * cl.x;
                e = v2; o = v3;
                v2 = e * ch.x - o * ch.y; v3 = e * ch.y + o * ch.x;
            }
            if (docvt) { v0 = tf32r(v0); v1 = tf32r(v1); v2 = tf32r(v2); v3 = tf32r(v3); }
            *(float2*)(C + (size_t)rlo * D_ + col) = make_float2(v0, v1);
            *(float2*)(C + (size_t)rhi * D_ + col) = make_float2(v2, v3);
        }
    }
}

// ===========================================================================
// V transpose: g_v [b*SKV+s][h*64+d]  ->  g_vt [(b*H+h)*64+d][s]
// ===========================================================================
__global__ __launch_bounds__(256) void transpose_v(
    const float* __restrict__ V, float* __restrict__ Vt)
{
    __shared__ float ts[64 * 68];
    const int tb = blockIdx.x * 64, h = blockIdx.y, b = blockIdx.z;
    const int tid = threadIdx.x;
    const float* src = V + ((size_t)(b * SKV_ + tb)) * D_ + h * HD_;
#pragma unroll
    for (int j = 0; j < 4; j++) {
        const int idx = tid + 256 * j;
        const int r = idx >> 4, c4 = (idx & 15) << 2;
        float4 v = *(const float4*)(src + (size_t)r * D_ + c4);
        ts[(c4 + 0) * 68 + r] = v.x;
        ts[(c4 + 1) * 68 + r] = v.y;
        ts[(c4 + 2) * 68 + r] = v.z;
        ts[(c4 + 3) * 68 + r] = v.w;
    }
    __syncthreads();
    float* dst = Vt + ((size_t)((b * H_ + h) * HD_)) * SKV_ + tb;
#pragma unroll
    for (int j = 0; j < 4; j++) {
        const int idx = tid + 256 * j;
        const int d = idx >> 4, t4 = (idx & 15) << 2;
        float4 o = *(const float4*)&ts[d * 68 + t4];
        *(float4*)(dst + (size_t)d * SKV_ + t4) = o;
    }
}

// ===========================================================================
// Flash attention with tf32 mma.
// 128 threads (4 warps); q-tile 64 (16 rows/warp), kv-tile 64 (full width/warp).
// smem: [P/Q: 64x68][Kbuf0][Kbuf1][Vbuf0][Vbuf1]  (each 64x68 floats)
// ===========================================================================
#define AST 68
#define ATT_REGION (64 * AST)                 // floats
#define ATT_SMEM_BYTES (5 * ATT_REGION * 4)   // 87040

__global__ __launch_bounds__(128) void attn_mma(
    const float* __restrict__ Q, const float* __restrict__ K,
    const float* __restrict__ Vt, float* __restrict__ O)
{
    extern __shared__ float sm[];
    const int tid = threadIdx.x, lane = tid & 31, wid = tid >> 5;
    const int b = blockIdx.z, h = blockIdx.y, qBase = blockIdx.x * 64;
    const uint32_t smB = smem_u32(sm);

    const float* Qg = Q + ((size_t)(b * SQ_ + qBase)) * D_ + h * HD_;
    const float* Kg = K + ((size_t)(b * SKV_)) * D_ + h * HD_;
    const float* Vg = Vt + ((size_t)((b * H_ + h) * HD_)) * SKV_;

    const int rowOff = (lane & 7) + ((lane >> 3) & 1) * 8;
    const int aCol   = (lane >> 4) * 4;
    const int nOff   = (lane & 7) + (lane >> 4) * 8;
    const int bCol   = ((lane >> 3) & 1) * 4;

    // ---- stage Q into region 0, and K/V tile 0 into buf 0
#pragma unroll
    for (int j = 0; j < 8; j++) {
        const int idx = tid + 128 * j;
        const int r = idx >> 4, sg = idx & 15;
        cp16(smB + (uint32_t)(r * AST * 4 + sg * 16), Qg + (size_t)r * D_ + sg * 4);
    }
#pragma unroll
    for (int j = 0; j < 8; j++) {
        const int idx = tid + 128 * j;
        const int r = idx >> 4, sg = idx & 15;
        cp16(smB + (uint32_t)((ATT_REGION + r * AST) * 4 + sg * 16),
             Kg + (size_t)r * D_ + sg * 4);
        cp16(smB + (uint32_t)((3 * ATT_REGION + r * AST) * 4 + sg * 16),
             Vg + (size_t)r * SKV_ + sg * 4);
    }
    CP_COMMIT();
    CP_WAIT(0);
    __syncthreads();

    // ---- persistent Q fragments (scaled by softmax 1/8)
    uint32_t qf[8][4];
#pragma unroll
    for (int ks = 0; ks < 8; ks++) {
        ldsm4(qf[ks], smB + (uint32_t)(((wid * 16 + rowOff) * AST + ks * 8 + aCol) * 4));
#pragma unroll
        for (int r = 0; r < 4; r++)
            qf[ks][r] = __float_as_uint(__uint_as_float(qf[ks][r]) * 0.125f);
    }
    __syncthreads();   // Q region now reusable as P

    float m0r = -1e30f, m1r = -1e30f, l0r = 0.f, l1r = 0.f;
    float oac[8][4] = {};
    const int q2 = (lane & 3) << 1;
    const int prLo = wid * 16 + (lane >> 2);

    for (int it = 0; it < 32; it++) {
        const int buf = it & 1;
        if (it + 1 < 32) {   // prefetch next K/V tile
            const float* kp = Kg + (size_t)((it + 1) * 64) * D_;
            const float* vp = Vg + (it + 1) * 64;
            const uint32_t kb = smB + (uint32_t)((1 + (buf ^ 1)) * ATT_REGION * 4);
            const uint32_t vb = smB + (uint32_t)((3 + (buf ^ 1)) * ATT_REGION * 4);
#pragma unroll
            for (int j = 0; j < 8; j++) {
                const int idx = tid + 128 * j;
                const int r = idx >> 4, sg = idx & 15;
                cp16(kb + (uint32_t)(r * AST * 4 + sg * 16), kp + (size_t)r * D_ + sg * 4);
                cp16(vb + (uint32_t)(r * AST * 4 + sg * 16), vp + (size_t)r * SKV_ + sg * 4);
            }
            CP_COMMIT();
            CP_WAIT(1);
        } else {
            CP_WAIT(0);
        }
        __syncthreads();

        // ---- S = (Q/8) K^T
        const uint32_t kb = smB + (uint32_t)((1 + buf) * ATT_REGION * 4);
        float sc[8][4] = {};
#pragma unroll
        for (int ks = 0; ks < 8; ks++) {
            uint32_t bf[4][4];
#pragma unroll
            for (int p = 0; p < 4; p++)
                ldsm4(bf[p], kb + (uint32_t)(((16 * p + nOff) * AST + ks * 8 + bCol) * 4));
#pragma unroll
            for (int p = 0; p < 4; p++) {
                mma_tf32(sc[2 * p],     qf[ks], &bf[p][0]);
                mma_tf32(sc[2 * p + 1], qf[ks], &bf[p][2]);
            }
        }

        // ---- online softmax (rows warp-exclusive; 4 lanes share a row)
        float mx0 = -1e30f, mx1 = -1e30f;
#pragma unroll
        for (int j = 0; j < 8; j++) {
            mx0 = fmaxf(mx0, fmaxf(sc[j][0], sc[j][1]));
            mx1 = fmaxf(mx1, fmaxf(sc[j][2], sc[j][3]));
        }
        mx0 = fmaxf(mx0, __shfl_xor_sync(0xFFFFFFFFu, mx0, 1));
        mx0 = fmaxf(mx0, __shfl_xor_sync(0xFFFFFFFFu, mx0, 2));
        mx1 = fmaxf(mx1, __shfl_xor_sync(0xFFFFFFFFu, mx1, 1));
        mx1 = fmaxf(mx1, __shfl_xor_sync(0xFFFFFFFFu, mx1, 2));
        const float mn0 = fmaxf(m0r, mx0), mn1 = fmaxf(m1r, mx1);
        const float c0 = __expf(m0r - mn0), c1 = __expf(m1r - mn1);
        float s0 = 0.f, s1 = 0.f;
#pragma unroll
        for (int j = 0; j < 8; j++) {
            float p0 = __expf(sc[j][0] - mn0);
            float p1 = __expf(sc[j][1] - mn0);
            float p2 = __expf(sc[j][2] - mn1);
            float p3 = __expf(sc[j][3] - mn1);
            s0 += p0 + p1; s1 += p2 + p3;
            sc[j][0] = tf32r(p0); sc[j][1] = tf32r(p1);
            sc[j][2] = tf32r(p2); sc[j][3] = tf32r(p3);
        }
        s0 += __shfl_xor_sync(0xFFFFFFFFu, s0, 1);
        s0 += __shfl_xor_sync(0xFFFFFFFFu, s0, 2);
        s1 += __shfl_xor_sync(0xFFFFFFFFu, s1, 1);
        s1 += __shfl_xor_sync(0xFFFFFFFFu, s1, 2);
        l0r = l0r * c0 + s0; l1r = l1r * c1 + s1;
        m0r = mn0; m1r = mn1;

        // ---- P -> smem (warp-private region rows wid*16..wid*16+15)
        __syncwarp();
#pragma unroll
        for (int j = 0; j < 8; j++) {
            *(float2*)&sm[prLo * AST + j * 8 + q2]       = make_float2(sc[j][0], sc[j][1]);
            *(float2*)&sm[(prLo + 8) * AST + j * 8 + q2] = make_float2(sc[j][2], sc[j][3]);
        }
        __syncwarp();

        // ---- rescale O, then O += P V
#pragma unroll
        for (int j = 0; j < 8; j++) {
            oac[j][0] *= c0; oac[j][1] *= c0;
            oac[j][2] *= c1; oac[j][3] *= c1;
        }
        const uint32_t vb = smB + (uint32_t)((3 + buf) * ATT_REGION * 4);
#pragma unroll
        for (int kc = 0; kc < 8; kc++) {
            uint32_t af[4];
            ldsm4(af, smB + (uint32_t)(((wid * 16 + rowOff) * AST + kc * 8 + aCol) * 4));
            uint32_t bf[4][4];
#pragma unroll
            for (int p = 0; p < 4; p++)
                ldsm4(bf[p], vb + (uint32_t)(((16 * p + nOff) * AST + kc * 8 + bCol) * 4));
#pragma unroll
            for (int p = 0; p < 4; p++) {
                mma_tf32(oac[2 * p],     af, &bf[p][0]);
                mma_tf32(oac[2 * p + 1], af, &bf[p][2]);
            }
        }
        __syncthreads();
    }

    // ---- normalize + store
    const float i0 = 1.0f / l0r, i1 = 1.0f / l1r;
    const int rlo = qBase + wid * 16 + (lane >> 2), rhi = rlo + 8;
    float* Og = O + ((size_t)(b * SQ_)) * D_ + h * HD_;
#pragma unroll
    for (int j = 0; j < 8; j++) {
        const int col = j * 8 + q2;
        *(float2*)&Og[(size_t)rlo * D_ + col] =
            make_float2(oac[j][0] * i0, oac[j][1] * i0);
        *(float2*)&Og[(size_t)rhi * D_ + col] =
            make_float2(oac[j][2] * i1, oac[j][3] * i1);
    }
}

// ---------------------------------------------------------------------------
extern "C" void kernel_launch(void* const* d_in, const int* in_sizes, int n_in,
                              void* d_out, int out_size)
{
    const float* x_q  = (const float*)d_in[0];
    const float* x_kv = (const float*)d_in[1];
    const float* wq   = (const float*)d_in[2];
    const float* bq   = (const float*)d_in[3];
    const float* wk   = (const float*)d_in[4];
    const float* bk   = (const float*)d_in[5];
    const float* wv   = (const float*)d_in[6];
    const float* bv   = (const float*)d_in[7];
    const float* wo   = (const float*)d_in[8];
    const float* bo   = (const float*)d_in[9];
    float* out = (float*)d_out;

    float *gq, *gk, *gv, *gvt, *gctx;
    float2* grope;
    cudaGetSymbolAddress((void**)&gq, g_q);
    cudaGetSymbolAddress((void**)&gk, g_k);
    cudaGetSymbolAddress((void**)&gv, g_v);
    cudaGetSymbolAddress((void**)&gvt, g_vt);
    cudaGetSymbolAddress((void**)&gctx, g_ctx);
    cudaGetSymbolAddress((void**)&grope, g_rope);

    static int configured = 0;
    if (!configured) {
        cudaFuncSetAttribute(gemm_mma,
            cudaFuncAttributeMaxDynamicSharedMemorySize, GEMM_SMEM_BYTES);
        cudaFuncSetAttribute(attn_mma,
            cudaFuncAttributeMaxDynamicSharedMemorySize, ATT_SMEM_BYTES);
        configured = 1;
    }

    rope_init_kernel<<<(SQ_ * 32 + 255) / 256, 256>>>(grope);

    dim3 gg(D_ / 128, M_ / 128);  // (8, 32)
    gemm_mma<<<gg, 256, GEMM_SMEM_BYTES>>>(x_q,  wq, bq, gq, 1, 1, grope);
    gemm_mma<<<gg, 256, GEMM_SMEM_BYTES>>>(x_kv, wk, bk, gk, 1, 1, grope);
    gemm_mma<<<gg, 256, GEMM_SMEM_BYTES>>>(x_kv, wv, bv, gv, 0, 1, grope);

    dim3 gt(SKV_ / 64, H_, B_);
    transpose_v<<<gt, 256>>>(gv, gvt);

    dim3 ga(SQ_ / 64, H_, B_);
    attn_mma<<<ga, 128, ATT_SMEM_BYTES>>>(gq, gk, gvt, gctx);

    gemm_mma<<<gg, 256, GEMM_SMEM_BYTES>>>(gctx, wo, bo, out, 0, 0, grope);
}